// round 1
// baseline (speedup 1.0000x reference)
#include <cuda_runtime.h>
#include <math.h>

#define BB 64
#define TT 4096
#define DD 256
#define UU 256

// scratch for per-(b,t) scores (device global: allocation-free rule)
__device__ float g_scores[BB * TT];

// ---------------------------------------------------------------------------
// Phase 1: fused GEMM  S[row] = sum_u tanh( (X @ (W1+W2))[row,u] ) * v[u]
// Block: 256 threads, tile = 64 rows x 256 cols, BK = 32.
// Each thread owns an 8x8 microtile. warp = 8 rows, 32 lanes split 256 cols.
// ---------------------------------------------------------------------------
__global__ __launch_bounds__(256, 2)
void score_kernel(const float* __restrict__ X,
                  const float* __restrict__ W1,
                  const float* __restrict__ W2,
                  const float* __restrict__ v)
{
    __shared__ float Xs[32][65];    // [k][row], padded to dodge store conflicts
    __shared__ float Ws[32][256];   // [k][u], W1+W2 fused at load
    __shared__ float sv[256];

    const int tid  = threadIdx.x;
    const int ty   = tid >> 5;   // warp id: rows ty*8 .. ty*8+7
    const int tx   = tid & 31;   // lane: cols tx*8 .. tx*8+7
    const long row0 = (long)blockIdx.x * 64;

    sv[tid] = v[tid];

    float acc[8][8];
#pragma unroll
    for (int i = 0; i < 8; i++)
#pragma unroll
        for (int j = 0; j < 8; j++) acc[i][j] = 0.f;

    for (int k0 = 0; k0 < DD; k0 += 32) {
        __syncthreads();
        // load X tile: 64 rows x 32 k (as float4), transpose into Xs[k][row]
#pragma unroll
        for (int it = 0; it < 2; it++) {
            int l  = tid + it * 256;      // 0..511
            int r  = l >> 3;              // 0..63
            int c4 = (l & 7) << 2;        // 0,4,..,28
            float4 xv = *(const float4*)(X + (row0 + r) * DD + k0 + c4);
            Xs[c4 + 0][r] = xv.x;
            Xs[c4 + 1][r] = xv.y;
            Xs[c4 + 2][r] = xv.z;
            Xs[c4 + 3][r] = xv.w;
        }
        // load W tile: 32 k x 256 u, fusing W1+W2
#pragma unroll
        for (int it = 0; it < 8; it++) {
            int l  = tid + it * 256;      // 0..2047 (float4 index)
            int kk = l >> 6;              // 0..31
            int c4 = (l & 63) << 2;       // 0..252
            float4 a = *(const float4*)(W1 + (size_t)(k0 + kk) * UU + c4);
            float4 b = *(const float4*)(W2 + (size_t)(k0 + kk) * UU + c4);
            float4 w;
            w.x = a.x + b.x; w.y = a.y + b.y; w.z = a.z + b.z; w.w = a.w + b.w;
            *(float4*)&Ws[kk][c4] = w;
        }
        __syncthreads();

#pragma unroll
        for (int k = 0; k < 32; k++) {
            float a[8], b[8];
#pragma unroll
            for (int i = 0; i < 8; i++) a[i] = Xs[k][ty * 8 + i];
            float4 b0 = *(float4*)&Ws[k][tx * 8];
            float4 b1 = *(float4*)&Ws[k][tx * 8 + 4];
            b[0] = b0.x; b[1] = b0.y; b[2] = b0.z; b[3] = b0.w;
            b[4] = b1.x; b[5] = b1.y; b[6] = b1.z; b[7] = b1.w;
#pragma unroll
            for (int i = 0; i < 8; i++)
#pragma unroll
                for (int j = 0; j < 8; j++)
                    acc[i][j] = fmaf(a[i], b[j], acc[i][j]);
        }
    }

    // epilogue: tanh, dot with v, warp-reduce across the 32 lanes (256 cols)
#pragma unroll
    for (int i = 0; i < 8; i++) {
        float p = 0.f;
#pragma unroll
        for (int j = 0; j < 8; j++)
            p += tanhf(acc[i][j]) * sv[tx * 8 + j];
#pragma unroll
        for (int off = 16; off > 0; off >>= 1)
            p += __shfl_xor_sync(0xffffffffu, p, off);
        if (tx == 0)
            g_scores[row0 + ty * 8 + i] = p;
    }
}

// ---------------------------------------------------------------------------
// Phase 2: softmax over T per batch, write attention weights
// ---------------------------------------------------------------------------
__global__ void softmax_kernel(float* __restrict__ weights)
{
    const int b   = blockIdx.x;
    const int tid = threadIdx.x;   // 256 threads, 16 elems each
    const float* s = g_scores + (size_t)b * TT;
    __shared__ float red[256];

    float m = -INFINITY;
#pragma unroll
    for (int i = 0; i < 16; i++) m = fmaxf(m, s[tid + i * 256]);
    red[tid] = m;
    __syncthreads();
    for (int st = 128; st > 0; st >>= 1) {
        if (tid < st) red[tid] = fmaxf(red[tid], red[tid + st]);
        __syncthreads();
    }
    m = red[0];
    __syncthreads();

    float e[16];
    float sum = 0.f;
#pragma unroll
    for (int i = 0; i < 16; i++) {
        e[i] = expf(s[tid + i * 256] - m);
        sum += e[i];
    }
    red[tid] = sum;
    __syncthreads();
    for (int st = 128; st > 0; st >>= 1) {
        if (tid < st) red[tid] += red[tid + st];
        __syncthreads();
    }
    const float inv = 1.f / red[0];
#pragma unroll
    for (int i = 0; i < 16; i++)
        weights[(size_t)b * TT + tid + i * 256] = e[i] * inv;
}

// ---------------------------------------------------------------------------
// Phase 3: context[b,d] = sum_t w[b,t] * X[b,t,d]
// One block per batch, 1024 threads: 4 T-segments x 256 d-columns. No atomics.
// ---------------------------------------------------------------------------
__global__ __launch_bounds__(1024)
void context_kernel(const float* __restrict__ X,
                    const float* __restrict__ w,
                    float* __restrict__ ctx)
{
    const int b   = blockIdx.x;
    const int d   = threadIdx.x & 255;
    const int seg = threadIdx.x >> 8;    // 0..3
    const float* xb = X + (size_t)b * TT * DD;
    const float* wb = w + (size_t)b * TT;

    float acc = 0.f;
    const int t0 = seg * 1024;
    for (int t = t0; t < t0 + 1024; t += 4) {
#pragma unroll
        for (int q = 0; q < 4; q++)
            acc = fmaf(wb[t + q], xb[(size_t)(t + q) * DD + d], acc);
    }

    __shared__ float red[1024];
    red[threadIdx.x] = acc;
    __syncthreads();
    if (seg == 0)
        ctx[(size_t)b * DD + d] = red[d] + red[d + 256] + red[d + 512] + red[d + 768];
}

// ---------------------------------------------------------------------------
extern "C" void kernel_launch(void* const* d_in, const int* in_sizes, int n_in,
                              void* d_out, int out_size)
{
    const float* X  = (const float*)d_in[0];
    const float* W1 = (const float*)d_in[1];
    const float* W2 = (const float*)d_in[2];
    const float* v  = (const float*)d_in[3];

    float* out     = (float*)d_out;
    float* ctx     = out;               // context_vector: B*D floats
    float* weights = out + BB * DD;     // attention_weights: B*T floats

    score_kernel<<<(BB * TT) / 64, 256>>>(X, W1, W2, v);
    softmax_kernel<<<BB, 256>>>(weights);
    context_kernel<<<BB, 1024>>>(X, weights, ctx);
}

// round 3
// speedup vs baseline: 2.1960x; 2.1960x over previous
#include <cuda_runtime.h>
#include <cuda_bf16.h>
#include <math.h>
#include <stdint.h>

#define BB 64
#define TT 4096
#define DD 256
#define UU 256

// ---------------- device-global scratch (allocation-free rule) -------------
__device__ float g_scores[BB * TT];
__device__ float g_cpart[8 * BB * DD];
__device__ __align__(16) __nv_bfloat16 g_WhT[UU * DD];   // (W1+W2)^T hi, [n][k]
__device__ __align__(16) __nv_bfloat16 g_WlT[UU * DD];   // (W1+W2)^T lo, [n][k]

// ---------------- smem layout for score kernel -----------------------------
#define KC     32            // k per chunk
#define KPAD   40            // padded row length (elems) -> 80B, conflict-free ldmatrix
#define ROWB   (KPAD * 2)    // bytes per row
#define A_H    0
#define A_L    10240         // 128 rows * 80B
#define W_H    20480
#define W_L    40960         // + 256 rows * 80B
#define BUFSZ  61440
#define RED_OFF 122880       // 128 rows * 8 warps * 4B = 4KB
#define SV_OFF  126976       // 256 floats
#define SM_TOTAL 128000

// ---------------- PTX helpers (plain sm_103-legal: no 'a' features) --------
__device__ __forceinline__ uint32_t smem_u32(const void* p) {
    uint32_t a;
    asm("{ .reg .u64 t; cvta.to.shared.u64 t, %1; cvt.u32.u64 %0, t; }"
        : "=r"(a) : "l"(p));
    return a;
}
__device__ __forceinline__ void ldm4(uint32_t* r, uint32_t addr) {
    asm volatile("ldmatrix.sync.aligned.m8n8.x4.shared.b16 {%0,%1,%2,%3}, [%4];"
                 : "=r"(r[0]), "=r"(r[1]), "=r"(r[2]), "=r"(r[3]) : "r"(addr));
}
__device__ __forceinline__ void mma16816(float* c, const uint32_t* a, const uint32_t* b) {
    asm volatile(
        "mma.sync.aligned.m16n8k16.row.col.f32.bf16.bf16.f32 "
        "{%0,%1,%2,%3},{%4,%5,%6,%7},{%8,%9},{%0,%1,%2,%3};"
        : "+f"(c[0]), "+f"(c[1]), "+f"(c[2]), "+f"(c[3])
        : "r"(a[0]), "r"(a[1]), "r"(a[2]), "r"(a[3]), "r"(b[0]), "r"(b[1]));
}
__device__ __forceinline__ void cpa16(uint32_t dst, const void* src) {
    asm volatile("cp.async.ca.shared.global [%0], [%1], 16;" :: "r"(dst), "l"(src));
}
#define CP_COMMIT() asm volatile("cp.async.commit_group;" ::: "memory")
#define CP_WAIT0()  asm volatile("cp.async.wait_group 0;" ::: "memory")

__device__ __forceinline__ uint32_t pack_bf2(float a, float b) {
    __nv_bfloat162 t = __floats2bfloat162_rn(a, b);
    return *(uint32_t*)&t;
}
__device__ __forceinline__ float fast_tanh(float q) {
    float e = __expf(2.f * q);
    return 1.f - __fdividef(2.f, e + 1.f);   // exact limits at +/-inf
}

// ---------------- phase 0: fuse + split + transpose weights ----------------
__global__ void prep_w(const float* __restrict__ W1, const float* __restrict__ W2)
{
    int idx = blockIdx.x * 256 + threadIdx.x;   // idx = k*256 + u
    int k = idx >> 8, u = idx & 255;
    float w = W1[idx] + W2[idx];
    __nv_bfloat16 h = __float2bfloat16(w);
    __nv_bfloat16 l = __float2bfloat16(w - __bfloat162float(h));
    g_WhT[u * DD + k] = h;
    g_WlT[u * DD + k] = l;
}

// ---------------- phase 1: HMMA GEMM + tanh/v epilogue ---------------------
// 512 threads, tile M=128 x N=256, K chunks of 32 (double-buffered).
// 16 warps: wg=wid>>3 picks row-half (64 rows), wn=wid&7 picks 32-col slice.
__global__ void __launch_bounds__(512, 1)
score_mma_kernel(const float* __restrict__ X, const float* __restrict__ v)
{
    extern __shared__ char smem[];
    const uint32_t sb = smem_u32(smem);
    const int tid  = threadIdx.x;
    const int wid  = tid >> 5, lane = tid & 31;
    const int wg   = wid >> 3, wn = wid & 7;
    const long row0 = (long)blockIdx.x * 128;

    if (tid < 256) ((float*)(smem + SV_OFF))[tid] = v[tid];

    // A (X) prefetch assignment: thread -> (row, 8-k group)
    const int ar  = tid >> 2;                 // 0..127
    const int akg = tid & 3;                  // 0..3
    const float* aptr = X + (row0 + ar) * DD + akg * 8;
    const uint32_t a_rel = (uint32_t)(ar * ROWB + akg * 16);

    // W cp.async assignment: thread -> (n row, hi/lo)
    const int wrow = tid & 255;
    const int whl  = tid >> 8;                // 0:hi 1:lo
    const __nv_bfloat16* wsrc = (whl ? g_WlT : g_WhT) + (size_t)wrow * DD;
    const uint32_t w_rel = (uint32_t)((whl ? W_L : W_H) + wrow * ROWB);

    float c[4][4][4];
#pragma unroll
    for (int i = 0; i < 4; i++)
#pragma unroll
        for (int j = 0; j < 4; j++)
#pragma unroll
            for (int r = 0; r < 4; r++) c[i][j][r] = 0.f;

    // ldmatrix address components (chunk-invariant parts)
    const uint32_t a_ldm_rel = (uint32_t)((wg * 64 + (lane & 15)) * ROWB + (lane >> 4) * 16);
    const int nofs  = (lane & 7) + ((lane >> 4) & 1) * 8;
    const int khalf = (lane >> 3) & 1;
    const uint32_t b_ldm_rel0 = (uint32_t)(W_H + (wn * 32 + nofs) * ROWB + khalf * 16);

    // ---- prologue: chunk 0 in flight
    float4 f0 = *(const float4*)(aptr);
    float4 f1 = *(const float4*)(aptr + 4);
#pragma unroll
    for (int q = 0; q < 4; q++)
        cpa16(sb + w_rel + q * 16, (const char*)(wsrc) + q * 16);
    CP_COMMIT();

    for (int cch = 0; cch < 8; cch++) {
        const uint32_t buf = (cch & 1) * BUFSZ;
        // store A chunk (split fp32 -> bf16 hi/lo)
        {
            float h0 = __bfloat162float(__float2bfloat16(f0.x));
            float h1 = __bfloat162float(__float2bfloat16(f0.y));
            float h2 = __bfloat162float(__float2bfloat16(f0.z));
            float h3 = __bfloat162float(__float2bfloat16(f0.w));
            float h4 = __bfloat162float(__float2bfloat16(f1.x));
            float h5 = __bfloat162float(__float2bfloat16(f1.y));
            float h6 = __bfloat162float(__float2bfloat16(f1.z));
            float h7 = __bfloat162float(__float2bfloat16(f1.w));
            uint4 hv, lv;
            hv.x = pack_bf2(h0, h1); hv.y = pack_bf2(h2, h3);
            hv.z = pack_bf2(h4, h5); hv.w = pack_bf2(h6, h7);
            lv.x = pack_bf2(f0.x - h0, f0.y - h1);
            lv.y = pack_bf2(f0.z - h2, f0.w - h3);
            lv.z = pack_bf2(f1.x - h4, f1.y - h5);
            lv.w = pack_bf2(f1.z - h6, f1.w - h7);
            *(uint4*)(smem + buf + A_H + a_rel) = hv;
            *(uint4*)(smem + buf + A_L + a_rel) = lv;
        }
        CP_WAIT0();
        __syncthreads();

        if (cch < 7) {  // prefetch next chunk
            const float* ap = aptr + (cch + 1) * KC;
            f0 = *(const float4*)(ap);
            f1 = *(const float4*)(ap + 4);
            const uint32_t nbuf = ((cch + 1) & 1) * BUFSZ;
            const char* ws = (const char*)(wsrc + (cch + 1) * KC);
#pragma unroll
            for (int q = 0; q < 4; q++)
                cpa16(sb + nbuf + w_rel + q * 16, ws + q * 16);
            CP_COMMIT();
        }

        // compute: 2 k16-steps on this chunk
#pragma unroll
        for (int s = 0; s < 2; s++) {
            uint32_t bh[8], bl[8];
#pragma unroll
            for (int jp = 0; jp < 2; jp++) {
                uint32_t ba = sb + buf + b_ldm_rel0 + jp * 16 * ROWB + s * 32;
                ldm4(&bh[jp * 4], ba);
                ldm4(&bl[jp * 4], ba + (W_L - W_H));
            }
#pragma unroll
            for (int i = 0; i < 4; i++) {
                uint32_t ah[4], al[4];
                uint32_t aa = sb + buf + A_H + a_ldm_rel + i * 16 * ROWB + s * 32;
                ldm4(ah, aa);
                ldm4(al, aa + (A_L - A_H));
#pragma unroll
                for (int j = 0; j < 4; j++) {
                    mma16816(c[i][j], ah, &bh[j * 2]);
                    mma16816(c[i][j], ah, &bl[j * 2]);
                    mma16816(c[i][j], al, &bh[j * 2]);
                }
            }
        }
    }

    // ---- epilogue: score[row] = sum_col tanh(C[row,col]) * v[col]
    const float* sv = (const float*)(smem + SV_OFF);
    float mv0[4], mv1[4];
#pragma unroll
    for (int j = 0; j < 4; j++) {
        int col = wn * 32 + j * 8 + (lane & 3) * 2;
        mv0[j] = sv[col];
        mv1[j] = sv[col + 1];
    }
    float* red = (float*)(smem + RED_OFF);
#pragma unroll
    for (int i = 0; i < 4; i++) {
#pragma unroll
        for (int rh = 0; rh < 2; rh++) {
            float p = 0.f;
#pragma unroll
            for (int j = 0; j < 4; j++) {
                p = fmaf(fast_tanh(c[i][j][rh * 2 + 0]), mv0[j], p);
                p = fmaf(fast_tanh(c[i][j][rh * 2 + 1]), mv1[j], p);
            }
            p += __shfl_xor_sync(0xffffffffu, p, 1);
            p += __shfl_xor_sync(0xffffffffu, p, 2);
            if ((lane & 3) == 0)
                red[(wg * 64 + i * 16 + rh * 8 + (lane >> 2)) * 8 + wn] = p;
        }
    }
    __syncthreads();
    if (tid < 128) {
        float s = 0.f;
#pragma unroll
        for (int w = 0; w < 8; w++) s += red[tid * 8 + w];
        g_scores[row0 + tid] = s;
    }
}

// ---------------- phase 2: softmax over T per batch -------------------------
__global__ void softmax_kernel(float* __restrict__ weights)
{
    const int b   = blockIdx.x;
    const int tid = threadIdx.x;
    const float* s = g_scores + (size_t)b * TT;
    __shared__ float red[256];

    float m = -INFINITY;
#pragma unroll
    for (int i = 0; i < 16; i++) m = fmaxf(m, s[tid + i * 256]);
    red[tid] = m;
    __syncthreads();
    for (int st = 128; st > 0; st >>= 1) {
        if (tid < st) red[tid] = fmaxf(red[tid], red[tid + st]);
        __syncthreads();
    }
    m = red[0];
    __syncthreads();

    float e[16];
    float sum = 0.f;
#pragma unroll
    for (int i = 0; i < 16; i++) {
        e[i] = expf(s[tid + i * 256] - m);
        sum += e[i];
    }
    red[tid] = sum;
    __syncthreads();
    for (int st = 128; st > 0; st >>= 1) {
        if (tid < st) red[tid] += red[tid + st];
        __syncthreads();
    }
    const float inv = 1.f / red[0];
#pragma unroll
    for (int i = 0; i < 16; i++)
        weights[(size_t)b * TT + tid + i * 256] = e[i] * inv;
}

// ---------------- phase 3: context, 2-stage (512-way parallel, no atomics) --
__global__ void ctx_part_kernel(const float* __restrict__ X,
                                const float* __restrict__ w)
{
    const int b   = blockIdx.x;
    const int seg = blockIdx.y;                 // 0..7, 512 timesteps each
    const int d   = threadIdx.x;
    const float* xb = X + ((size_t)b * TT + seg * 512) * DD;
    const float* wb = w + (size_t)b * TT + seg * 512;

    float acc = 0.f;
    for (int t = 0; t < 512; t += 4) {
#pragma unroll
        for (int q = 0; q < 4; q++)
            acc = fmaf(wb[t + q], xb[(size_t)(t + q) * DD + d], acc);
    }
    g_cpart[((size_t)seg * BB + b) * DD + d] = acc;
}

__global__ void ctx_final_kernel(float* __restrict__ ctx)
{
    const int b = blockIdx.x, d = threadIdx.x;
    float s = 0.f;
#pragma unroll
    for (int seg = 0; seg < 8; seg++)
        s += g_cpart[((size_t)seg * BB + b) * DD + d];
    ctx[(size_t)b * DD + d] = s;
}

// ---------------------------------------------------------------------------
extern "C" void kernel_launch(void* const* d_in, const int* in_sizes, int n_in,
                              void* d_out, int out_size)
{
    const float* X  = (const float*)d_in[0];
    const float* W1 = (const float*)d_in[1];
    const float* W2 = (const float*)d_in[2];
    const float* v  = (const float*)d_in[3];

    float* out     = (float*)d_out;
    float* ctx     = out;               // context_vector: B*D floats
    float* weights = out + BB * DD;     // attention_weights: B*T floats

    cudaFuncSetAttribute(score_mma_kernel,
                         cudaFuncAttributeMaxDynamicSharedMemorySize, SM_TOTAL);

    prep_w<<<256, 256>>>(W1, W2);
    score_mma_kernel<<<(BB * TT) / 128, 512, SM_TOTAL>>>(X, v);
    softmax_kernel<<<BB, 256>>>(weights);
    ctx_part_kernel<<<dim3(BB, 8), 256>>>(X, weights);
    ctx_final_kernel<<<BB, 256>>>(ctx);
}